// round 4
// baseline (speedup 1.0000x reference)
#include <cuda_runtime.h>
#include <math.h>

#define SLEN 2048
#define DIN  1024
#define DOUT 1024
#define NH   16
#define HD   64
#define BATCH 2
#define ROWS (BATCH*SLEN)   // 4096

// Scratch (allocation-free): Q, K, V, CTX, each [ROWS, DOUT] fp32
__device__ float g_q[(size_t)ROWS*DOUT];
__device__ float g_k[(size_t)ROWS*DOUT];
__device__ float g_v[(size_t)ROWS*DOUT];
__device__ float g_ctx[(size_t)ROWS*DOUT];

// ---------------------------------------------------------------------------
// SGEMM: C[M,N] = A[M,K] @ B[K,N], all row-major fp32.
// BM=BN=128, BK=8, 256 threads, 8x8 micro-tile per thread.
// M,N,K are multiples of tile sizes here (4096/1024/1024) -> no bounds checks.
// ---------------------------------------------------------------------------
#define BM 128
#define BN 128
#define BK 8
#define TM 8
#define TN 8

__global__ __launch_bounds__(256) void sgemm(const float* __restrict__ A,
                                             const float* __restrict__ Bm,
                                             float* __restrict__ C,
                                             int M, int N, int K) {
    __shared__ float As[BK][BM];
    __shared__ float Bs[BK][BN];
    const int tid = threadIdx.x;
    const int block_row = blockIdx.y * BM;
    const int block_col = blockIdx.x * BN;
    const int tr = tid / 16;       // 0..15
    const int tc = tid % 16;       // 0..15

    float acc[TM][TN];
#pragma unroll
    for (int i = 0; i < TM; i++)
#pragma unroll
        for (int j = 0; j < TN; j++) acc[i][j] = 0.f;

    const int aRow = tid / 2;            // 0..127
    const int aCol = (tid & 1) * 4;      // 0 or 4
    const int bRow = tid / 32;           // 0..7
    const int bCol = (tid & 31) * 4;     // 0..124

    const float* Ab = A + (size_t)block_row * K;
    const float* Bb = Bm + block_col;

    for (int k0 = 0; k0 < K; k0 += BK) {
        float4 av = *(const float4*)(Ab + (size_t)aRow * K + k0 + aCol);
        As[aCol + 0][aRow] = av.x;
        As[aCol + 1][aRow] = av.y;
        As[aCol + 2][aRow] = av.z;
        As[aCol + 3][aRow] = av.w;
        float4 bv = *(const float4*)(Bb + (size_t)(k0 + bRow) * N + bCol);
        *(float4*)&Bs[bRow][bCol] = bv;
        __syncthreads();
#pragma unroll
        for (int k = 0; k < BK; k++) {
            float rm[TM], rn[TN];
#pragma unroll
            for (int i = 0; i < TM; i++) rm[i] = As[k][tr * TM + i];
#pragma unroll
            for (int j = 0; j < TN; j++) rn[j] = Bs[k][tc * TN + j];
#pragma unroll
            for (int i = 0; i < TM; i++)
#pragma unroll
                for (int j = 0; j < TN; j++) acc[i][j] += rm[i] * rn[j];
        }
        __syncthreads();
    }

#pragma unroll
    for (int i = 0; i < TM; i++) {
        float* Crow = C + (size_t)(block_row + tr * TM + i) * N + block_col + tc * TN;
#pragma unroll
        for (int j = 0; j < TN; j += 4) {
            *(float4*)(Crow + j) =
                make_float4(acc[i][j], acc[i][j + 1], acc[i][j + 2], acc[i][j + 3]);
        }
    }
}

// ---------------------------------------------------------------------------
// Flash attention over contiguous per-(b,h) chunks of [SLEN, HD].
// Reference reshape is a pure view: head h of batch b = rows [h*128,(h+1)*128)
// of the [S, DOUT] projection -> contiguous [SLEN, HD] chunk per (b,h).
// grid.x = SLEN/BR query tiles, grid.y = BATCH*NH chunks. 256 threads.
// Thread (r = tid/4, c4 = tid&3):
//   QK phase: owns scores j = c4 + 4*i (i=0..7)   [BC=32 keys per tile]
//   PV phase: owns dims  d' = (c4+4g)*4 + u
// PADQ/PADP are multiples of 4 so float4 smem accesses stay 16B-aligned.
// Static smem = 44,032 B -> no cudaFuncSetAttribute needed.
// ---------------------------------------------------------------------------
#define BR 64
#define BC 32
#define PADQ 68
#define PADP 36

__global__ __launch_bounds__(256) void attn_kernel(const float* __restrict__ q,
                                                   const float* __restrict__ k,
                                                   const float* __restrict__ v,
                                                   float* __restrict__ ctx) {
    __shared__ float Qs[BR * PADQ];
    __shared__ float Ks[BC * PADQ];
    __shared__ float Vs[BC * PADQ];
    __shared__ float Ps[BR * PADP];

    const int tid = threadIdx.x;
    const int r   = tid >> 2;          // 0..63 query row in tile
    const int c4  = tid & 3;
    const int qx  = blockIdx.x;
    const size_t chunk = (size_t)blockIdx.y * (SLEN * HD);
    const int qi0 = qx * BR;

    // Load Q tile (64x64): thread (r,c4) loads 16 floats of row r
    const float* qg = q + chunk + (size_t)qi0 * HD;
#pragma unroll
    for (int u = 0; u < 4; u++) {
        *(float4*)&Qs[r * PADQ + c4 * 16 + u * 4] =
            *(const float4*)(qg + r * HD + c4 * 16 + u * 4);
    }

    // K/V loaders: 32 rows x 64 cols, 256 threads -> 8 floats (2 float4) each
    const int lr = tid >> 3;           // 0..31
    const int lc = (tid & 7) * 8;      // 0,8,...,56

    float o[16];
#pragma unroll
    for (int i = 0; i < 16; i++) o[i] = 0.f;
    float mval = -1e30f, lsum = 0.f;

    const int ntiles = (qi0 + BR) / BC;   // causal frontier in BC-tiles
    for (int kt = 0; kt < ntiles; kt++) {
        const int kj0 = kt * BC;
        __syncthreads();   // protect Ks/Vs from previous iteration readers
        const float* kg = k + chunk + (size_t)kj0 * HD;
        const float* vg = v + chunk + (size_t)kj0 * HD;
        *(float4*)&Ks[lr * PADQ + lc]     = *(const float4*)(kg + lr * HD + lc);
        *(float4*)&Ks[lr * PADQ + lc + 4] = *(const float4*)(kg + lr * HD + lc + 4);
        *(float4*)&Vs[lr * PADQ + lc]     = *(const float4*)(vg + lr * HD + lc);
        *(float4*)&Vs[lr * PADQ + lc + 4] = *(const float4*)(vg + lr * HD + lc + 4);
        __syncthreads();

        // ---- scores: s[i] = dot(Q[r,:], K[c4+4i,:]) ----
        float sreg[8];
#pragma unroll
        for (int i = 0; i < 8; i++) sreg[i] = 0.f;
#pragma unroll
        for (int d = 0; d < HD; d += 4) {
            float4 qv = *(const float4*)&Qs[r * PADQ + d];
#pragma unroll
            for (int i = 0; i < 8; i++) {
                const int j = c4 + 4 * i;
                float4 kv = *(const float4*)&Ks[j * PADQ + d];
                sreg[i] += qv.x * kv.x + qv.y * kv.y + qv.z * kv.z + qv.w * kv.w;
            }
        }

        // ---- scale + causal mask + tile max ----
        float tmax = -1e30f;
#pragma unroll
        for (int i = 0; i < 8; i++) {
            const int j = c4 + 4 * i;
            float sv = sreg[i] * 0.125f;          // 1/sqrt(64)
            if (kj0 + j > qi0 + r) sv = -1e30f;   // causal
            sreg[i] = sv;
            tmax = fmaxf(tmax, sv);
        }
        tmax = fmaxf(tmax, __shfl_xor_sync(0xffffffffu, tmax, 1));
        tmax = fmaxf(tmax, __shfl_xor_sync(0xffffffffu, tmax, 2));

        const float mnew = fmaxf(mval, tmax);
        const float corr = __expf(mval - mnew);

        float tsum = 0.f;
#pragma unroll
        for (int i = 0; i < 8; i++) {
            float p = __expf(sreg[i] - mnew);
            tsum += p;
            Ps[r * PADP + c4 + 4 * i] = p;
        }
        tsum += __shfl_xor_sync(0xffffffffu, tsum, 1);
        tsum += __shfl_xor_sync(0xffffffffu, tsum, 2);
        lsum = lsum * corr + tsum;
        mval = mnew;
#pragma unroll
        for (int i = 0; i < 16; i++) o[i] *= corr;

        __syncthreads();   // Ps fully written before PV reads

        // ---- PV: o[g*4+u] over d' = (c4+4g)*4+u ----
        for (int j = 0; j < BC; j++) {
            const float pj = Ps[r * PADP + j];
#pragma unroll
            for (int g = 0; g < 4; g++) {
                float4 vv = *(const float4*)&Vs[j * PADQ + (c4 + 4 * g) * 4];
                o[g * 4 + 0] += pj * vv.x;
                o[g * 4 + 1] += pj * vv.y;
                o[g * 4 + 2] += pj * vv.z;
                o[g * 4 + 3] += pj * vv.w;
            }
        }
    }

    const float inv = 1.f / lsum;
    float* og = ctx + chunk + (size_t)(qi0 + r) * HD;
#pragma unroll
    for (int g = 0; g < 4; g++) {
        *(float4*)(og + (c4 + 4 * g) * 4) =
            make_float4(o[g * 4 + 0] * inv, o[g * 4 + 1] * inv,
                        o[g * 4 + 2] * inv, o[g * 4 + 3] * inv);
    }
}

// ---------------------------------------------------------------------------
extern "C" void kernel_launch(void* const* d_in, const int* in_sizes, int n_in,
                              void* d_out, int out_size) {
    const float* x  = (const float*)d_in[0];
    const float* Wq = (const float*)d_in[1];
    const float* Wk = (const float*)d_in[2];
    const float* Wv = (const float*)d_in[3];
    const float* Wp = (const float*)d_in[4];
    float* out = (float*)d_out;

    float *q, *k, *v, *ctx;
    cudaGetSymbolAddress((void**)&q,   g_q);
    cudaGetSymbolAddress((void**)&k,   g_k);
    cudaGetSymbolAddress((void**)&v,   g_v);
    cudaGetSymbolAddress((void**)&ctx, g_ctx);

    dim3 gemm_grid(DOUT / BN, ROWS / BM);   // (8, 32)
    sgemm<<<gemm_grid, 256>>>(x, Wq, q, ROWS, DOUT, DIN);
    sgemm<<<gemm_grid, 256>>>(x, Wk, k, ROWS, DOUT, DIN);
    sgemm<<<gemm_grid, 256>>>(x, Wv, v, ROWS, DOUT, DIN);

    dim3 attn_grid(SLEN / BR, BATCH * NH);  // (32, 32)
    attn_kernel<<<attn_grid, 256>>>(q, k, v, ctx);

    sgemm<<<gemm_grid, 256>>>(ctx, Wp, out, ROWS, DOUT, DOUT);
}

// round 6
// speedup vs baseline: 1.3305x; 1.3305x over previous
#include <cuda_runtime.h>
#include <cuda_bf16.h>
#include <cstdint>
#include <math.h>

#define SLEN 2048
#define DIN  1024
#define DOUT 1024
#define NH   16
#define HD   64
#define BATCH 2
#define ROWS (BATCH*SLEN)   // 4096

// ---------------------------------------------------------------------------
// Scratch (allocation-free device globals)
// ---------------------------------------------------------------------------
__device__ float g_q[(size_t)ROWS*DOUT];
__device__ float g_k[(size_t)ROWS*DOUT];
__device__ float g_v[(size_t)ROWS*DOUT];
__device__ float g_ctx[(size_t)ROWS*DOUT];
// bf16 split operands
__device__ __nv_bfloat16 g_xb[(size_t)ROWS*DIN];
__device__ __nv_bfloat16 g_xs[(size_t)ROWS*DIN];
__device__ __nv_bfloat16 g_cb[(size_t)ROWS*DOUT];
__device__ __nv_bfloat16 g_cs[(size_t)ROWS*DOUT];
// transposed+split weights [N,K] K-major bf16
__device__ __nv_bfloat16 g_wqb[(size_t)DIN*DOUT], g_wqs[(size_t)DIN*DOUT];
__device__ __nv_bfloat16 g_wkb[(size_t)DIN*DOUT], g_wks[(size_t)DIN*DOUT];
__device__ __nv_bfloat16 g_wvb[(size_t)DIN*DOUT], g_wvs[(size_t)DIN*DOUT];
__device__ __nv_bfloat16 g_wpb[(size_t)DOUT*DOUT], g_wps[(size_t)DOUT*DOUT];

// ---------------------------------------------------------------------------
// mma.sync helpers (sm_80+, works on plain sm_100 target)
// ---------------------------------------------------------------------------
__device__ __forceinline__ uint32_t smem_u32(const void* p) {
    uint32_t a;
    asm("{ .reg .u64 t; cvta.to.shared.u64 t, %1; cvt.u32.u64 %0, t; }" : "=r"(a) : "l"(p));
    return a;
}
__device__ __forceinline__ void ldsm4(uint32_t* r, uint32_t addr) {
    asm volatile("ldmatrix.sync.aligned.m8n8.x4.shared.b16 {%0,%1,%2,%3}, [%4];"
                 : "=r"(r[0]), "=r"(r[1]), "=r"(r[2]), "=r"(r[3]) : "r"(addr));
}
__device__ __forceinline__ void ldsm2(uint32_t* r, uint32_t addr) {
    asm volatile("ldmatrix.sync.aligned.m8n8.x2.shared.b16 {%0,%1}, [%2];"
                 : "=r"(r[0]), "=r"(r[1]) : "r"(addr));
}
__device__ __forceinline__ void mma16816(float* d, const uint32_t* a, const uint32_t* b) {
    asm volatile("mma.sync.aligned.m16n8k16.row.col.f32.bf16.bf16.f32 "
                 "{%0,%1,%2,%3}, {%4,%5,%6,%7}, {%8,%9}, {%0,%1,%2,%3};"
                 : "+f"(d[0]), "+f"(d[1]), "+f"(d[2]), "+f"(d[3])
                 : "r"(a[0]), "r"(a[1]), "r"(a[2]), "r"(a[3]), "r"(b[0]), "r"(b[1]));
}
__device__ __forceinline__ uint32_t pack_bf2(float a, float b) {
    __nv_bfloat162 h;
    h.x = __float2bfloat16_rn(a);
    h.y = __float2bfloat16_rn(b);
    return *reinterpret_cast<uint32_t*>(&h);
}

// ---------------------------------------------------------------------------
// fsplit: fp32 -> (big, small) bf16 arrays, vectorized by 4
// ---------------------------------------------------------------------------
__global__ void fsplit(const float4* __restrict__ in, uint2* __restrict__ outb,
                       uint2* __restrict__ outs, int n4) {
    int i = blockIdx.x * blockDim.x + threadIdx.x;
    if (i >= n4) return;
    float4 v = in[i];
    __nv_bfloat16 bx = __float2bfloat16_rn(v.x), by = __float2bfloat16_rn(v.y);
    __nv_bfloat16 bz = __float2bfloat16_rn(v.z), bw = __float2bfloat16_rn(v.w);
    float sx = v.x - __bfloat162float(bx), sy = v.y - __bfloat162float(by);
    float sz = v.z - __bfloat162float(bz), sw = v.w - __bfloat162float(bw);
    uint2 ob, os;
    __nv_bfloat162 p0; p0.x = bx; p0.y = by;
    __nv_bfloat162 p1; p1.x = bz; p1.y = bw;
    ob.x = *reinterpret_cast<uint32_t*>(&p0);
    ob.y = *reinterpret_cast<uint32_t*>(&p1);
    os.x = pack_bf2(sx, sy);
    os.y = pack_bf2(sz, sw);
    outb[i] = ob;
    outs[i] = os;
}

// ---------------------------------------------------------------------------
// wsplit: W[K,N] fp32 -> WT big/small [N,K] bf16 (tiled transpose)
// ---------------------------------------------------------------------------
__global__ void wsplit(const float* __restrict__ W, __nv_bfloat16* __restrict__ tb,
                       __nv_bfloat16* __restrict__ ts) {
    __shared__ float t[32][33];
    const int n0 = blockIdx.x * 32, k0 = blockIdx.y * 32;
    const int tx = threadIdx.x, ty = threadIdx.y;   // (32, 8)
#pragma unroll
    for (int i = 0; i < 4; i++)
        t[ty + 8 * i][tx] = W[(size_t)(k0 + ty + 8 * i) * DOUT + n0 + tx];
    __syncthreads();
#pragma unroll
    for (int i = 0; i < 4; i++) {
        const int r = ty + 8 * i;               // local n
        float v = t[tx][r];                     // = W[k0+tx][n0+r]
        __nv_bfloat16 b = __float2bfloat16_rn(v);
        float s = v - __bfloat162float(b);
        tb[(size_t)(n0 + r) * DIN + k0 + tx] = b;
        ts[(size_t)(n0 + r) * DIN + k0 + tx] = __float2bfloat16_rn(s);
    }
}

// ---------------------------------------------------------------------------
// HMMA split-bf16 GEMM: C[M,1024] = A[M,1024] @ B^T, A (Ab,As) [M,K] row-major,
// B (Bb,Bs) [N,K] row-major (== col-major (k,n) for mma row.col).
// CTA 128x128, BK=32, 8 warps (2m x 4n), warp tile 64x32.
// 3 passes per fragment pair: ab*bb + ab*bs + as*bb (ss term dropped).
// ---------------------------------------------------------------------------
#define PA 40              // smem pitch in bf16 (80 B) -> conflict-free ldmatrix
#define BKC 32

__global__ __launch_bounds__(256) void gemm_mma(const __nv_bfloat16* __restrict__ Ab,
                                                const __nv_bfloat16* __restrict__ As,
                                                const __nv_bfloat16* __restrict__ Bb,
                                                const __nv_bfloat16* __restrict__ Bs,
                                                float* __restrict__ C) {
    __shared__ __nv_bfloat16 sAb[128 * PA];
    __shared__ __nv_bfloat16 sAs[128 * PA];
    __shared__ __nv_bfloat16 sBb[128 * PA];
    __shared__ __nv_bfloat16 sBs[128 * PA];

    const int tid = threadIdx.x;
    const int wid = tid >> 5, lane = tid & 31;
    const int n0 = blockIdx.x * 128, m0 = blockIdx.y * 128;
    const int warp_m = wid >> 2, warp_n = wid & 3;     // 2 x 4
    const int m0w = warp_m * 64, n0w = warp_n * 32;

    const uint32_t uAb = smem_u32(sAb), uAs = smem_u32(sAs);
    const uint32_t uBb = smem_u32(sBb), uBs = smem_u32(sBs);

    // ldmatrix lane address offsets (bytes) within each tile
    const int grp = lane >> 3;           // 0..3
    uint32_t aoff[4];
#pragma unroll
    for (int mt = 0; mt < 4; mt++) {
        const int rowA = m0w + mt * 16 + (grp & 1) * 8 + (lane & 7);
        aoff[mt] = (uint32_t)(rowA * (PA * 2) + (grp >> 1) * 16);
    }
    const int grpb = grp & 1;
    uint32_t boff[4];
#pragma unroll
    for (int nt = 0; nt < 4; nt++) {
        const int rowB = n0w + nt * 8 + (lane & 7);
        boff[nt] = (uint32_t)(rowB * (PA * 2) + grpb * 16);
    }

    float acc[16][4];
#pragma unroll
    for (int i = 0; i < 16; i++)
#pragma unroll
        for (int j = 0; j < 4; j++) acc[i][j] = 0.f;

    for (int ch = 0; ch < 1024 / BKC; ch++) {
        const int k0 = ch * BKC;
        __syncthreads();
        // load 4 tiles: 128 rows x 32 bf16 (64B = 4 uint4 per row)
#pragma unroll
        for (int it = tid; it < 512; it += 256) {
            const int row = it >> 2, u = it & 3;
            const uint32_t so = (uint32_t)(row * PA + u * 8);   // bf16 units
            *(uint4*)&sAb[so] = *((const uint4*)(Ab + (size_t)(m0 + row) * 1024 + k0) + u);
            *(uint4*)&sAs[so] = *((const uint4*)(As + (size_t)(m0 + row) * 1024 + k0) + u);
            *(uint4*)&sBb[so] = *((const uint4*)(Bb + (size_t)(n0 + row) * 1024 + k0) + u);
            *(uint4*)&sBs[so] = *((const uint4*)(Bs + (size_t)(n0 + row) * 1024 + k0) + u);
        }
        __syncthreads();

#pragma unroll
        for (int ks = 0; ks < 2; ks++) {
            const uint32_t kb = ks * 32;   // 16 bf16 = 32 B
            uint32_t fab[4][4], fas[4][4], fbb[4][2], fbs[4][2];
#pragma unroll
            for (int mt = 0; mt < 4; mt++) {
                ldsm4(fab[mt], uAb + aoff[mt] + kb);
                ldsm4(fas[mt], uAs + aoff[mt] + kb);
            }
#pragma unroll
            for (int nt = 0; nt < 4; nt++) {
                ldsm2(fbb[nt], uBb + boff[nt] + kb);
                ldsm2(fbs[nt], uBs + boff[nt] + kb);
            }
#pragma unroll
            for (int mt = 0; mt < 4; mt++)
#pragma unroll
                for (int nt = 0; nt < 4; nt++) {
                    float* d = acc[mt * 4 + nt];
                    mma16816(d, fab[mt], fbb[nt]);
                    mma16816(d, fab[mt], fbs[nt]);
                    mma16816(d, fas[mt], fbb[nt]);
                }
        }
    }

    // epilogue: m16n8 fragment layout
#pragma unroll
    for (int mt = 0; mt < 4; mt++)
#pragma unroll
        for (int nt = 0; nt < 4; nt++) {
            const float* d = acc[mt * 4 + nt];
            const int r0 = m0 + m0w + mt * 16 + (lane >> 2);
            const int c0 = n0 + n0w + nt * 8 + (lane & 3) * 2;
            *(float2*)(C + (size_t)r0 * 1024 + c0)       = make_float2(d[0], d[1]);
            *(float2*)(C + (size_t)(r0 + 8) * 1024 + c0) = make_float2(d[2], d[3]);
        }
}

// ---------------------------------------------------------------------------
// Flash attention (unchanged from passing R3 kernel)
// ---------------------------------------------------------------------------
#define BR 64
#define BC 32
#define PADQ 68
#define PADP 36

__global__ __launch_bounds__(256) void attn_kernel(const float* __restrict__ q,
                                                   const float* __restrict__ k,
                                                   const float* __restrict__ v,
                                                   float* __restrict__ ctx) {
    __shared__ float Qs[BR * PADQ];
    __shared__ float Ks[BC * PADQ];
    __shared__ float Vs[BC * PADQ];
    __shared__ float Ps[BR * PADP];

    const int tid = threadIdx.x;
    const int r   = tid >> 2;
    const int c4  = tid & 3;
    const int qx  = blockIdx.x;
    const size_t chunk = (size_t)blockIdx.y * (SLEN * HD);
    const int qi0 = qx * BR;

    const float* qg = q + chunk + (size_t)qi0 * HD;
#pragma unroll
    for (int u = 0; u < 4; u++) {
        *(float4*)&Qs[r * PADQ + c4 * 16 + u * 4] =
            *(const float4*)(qg + r * HD + c4 * 16 + u * 4);
    }

    const int lr = tid >> 3;
    const int lc = (tid & 7) * 8;

    float o[16];
#pragma unroll
    for (int i = 0; i < 16; i++) o[i] = 0.f;
    float mval = -1e30f, lsum = 0.f;

    const int ntiles = (qi0 + BR) / BC;
    for (int kt = 0; kt < ntiles; kt++) {
        const int kj0 = kt * BC;
        __syncthreads();
        const float* kg = k + chunk + (size_t)kj0 * HD;
        const float* vg = v + chunk + (size_t)kj0 * HD;
        *(float4*)&Ks[lr * PADQ + lc]     = *(const float4*)(kg + lr * HD + lc);
        *(float4*)&Ks[lr * PADQ + lc + 4] = *(const float4*)(kg + lr * HD + lc + 4);
        *(float4*)&Vs[lr * PADQ + lc]     = *(const float4*)(vg + lr * HD + lc);
        *(float4*)&Vs[lr * PADQ + lc + 4] = *(const float4*)(vg + lr * HD + lc + 4);
        __syncthreads();

        float sreg[8];
#pragma unroll
        for (int i = 0; i < 8; i++) sreg[i] = 0.f;
#pragma unroll
        for (int d = 0; d < HD; d += 4) {
            float4 qv = *(const float4*)&Qs[r * PADQ + d];
#pragma unroll
            for (int i = 0; i < 8; i++) {
                const int j = c4 + 4 * i;
                float4 kv = *(const float4*)&Ks[j * PADQ + d];
                sreg[i] += qv.x * kv.x + qv.y * kv.y + qv.z * kv.z + qv.w * kv.w;
            }
        }

        float tmax = -1e30f;
#pragma unroll
        for (int i = 0; i < 8; i++) {
            const int j = c4 + 4 * i;
            float sv = sreg[i] * 0.125f;
            if (kj0 + j > qi0 + r) sv = -1e30f;
            sreg[i] = sv;
            tmax = fmaxf(tmax, sv);
        }
        tmax = fmaxf(tmax, __shfl_xor_sync(0xffffffffu, tmax, 1));
        tmax = fmaxf(tmax, __shfl_xor_sync(0xffffffffu, tmax, 2));

        const float mnew = fmaxf(mval, tmax);
        const float corr = __expf(mval - mnew);

        float tsum = 0.f;
#pragma unroll
        for (int i = 0; i < 8; i++) {
            float p = __expf(sreg[i] - mnew);
            tsum += p;
            Ps[r * PADP + c4 + 4 * i] = p;
        }
        tsum += __shfl_xor_sync(0xffffffffu, tsum, 1);
        tsum += __shfl_xor_sync(0xffffffffu, tsum, 2);
        lsum = lsum * corr + tsum;
        mval = mnew;
#pragma unroll
        for (int i = 0; i < 16; i++) o[i] *= corr;

        __syncthreads();

        for (int j = 0; j < BC; j++) {
            const float pj = Ps[r * PADP + j];
#pragma unroll
            for (int g = 0; g < 4; g++) {
                float4 vv = *(const float4*)&Vs[j * PADQ + (c4 + 4 * g) * 4];
                o[g * 4 + 0] += pj * vv.x;
                o[g * 4 + 1] += pj * vv.y;
                o[g * 4 + 2] += pj * vv.z;
                o[g * 4 + 3] += pj * vv.w;
            }
        }
    }

    const float inv = 1.f / lsum;
    float* og = ctx + chunk + (size_t)(qi0 + r) * HD;
#pragma unroll
    for (int g = 0; g < 4; g++) {
        *(float4*)(og + (c4 + 4 * g) * 4) =
            make_float4(o[g * 4 + 0] * inv, o[g * 4 + 1] * inv,
                        o[g * 4 + 2] * inv, o[g * 4 + 3] * inv);
    }
}

// ---------------------------------------------------------------------------
extern "C" void kernel_launch(void* const* d_in, const int* in_sizes, int n_in,
                              void* d_out, int out_size) {
    const float* x  = (const float*)d_in[0];
    const float* Wq = (const float*)d_in[1];
    const float* Wk = (const float*)d_in[2];
    const float* Wv = (const float*)d_in[3];
    const float* Wp = (const float*)d_in[4];
    float* out = (float*)d_out;

    float *q, *k, *v, *ctx;
    cudaGetSymbolAddress((void**)&q,   g_q);
    cudaGetSymbolAddress((void**)&k,   g_k);
    cudaGetSymbolAddress((void**)&v,   g_v);
    cudaGetSymbolAddress((void**)&ctx, g_ctx);
    __nv_bfloat16 *xb, *xs, *cb, *cs;
    cudaGetSymbolAddress((void**)&xb, g_xb);
    cudaGetSymbolAddress((void**)&xs, g_xs);
    cudaGetSymbolAddress((void**)&cb, g_cb);
    cudaGetSymbolAddress((void**)&cs, g_cs);
    __nv_bfloat16 *wqb, *wqs, *wkb, *wks, *wvb, *wvs, *wpb, *wps;
    cudaGetSymbolAddress((void**)&wqb, g_wqb);
    cudaGetSymbolAddress((void**)&wqs, g_wqs);
    cudaGetSymbolAddress((void**)&wkb, g_wkb);
    cudaGetSymbolAddress((void**)&wks, g_wks);
    cudaGetSymbolAddress((void**)&wvb, g_wvb);
    cudaGetSymbolAddress((void**)&wvs, g_wvs);
    cudaGetSymbolAddress((void**)&wpb, g_wpb);
    cudaGetSymbolAddress((void**)&wps, g_wps);

    // 1. split x, transpose+split weights
    const int n4 = ROWS * DIN / 4;
    fsplit<<<n4 / 256, 256>>>((const float4*)x, (uint2*)xb, (uint2*)xs, n4);
    dim3 wgrid(32, 32), wblk(32, 8);
    wsplit<<<wgrid, wblk>>>(Wq, wqb, wqs);
    wsplit<<<wgrid, wblk>>>(Wk, wkb, wks);
    wsplit<<<wgrid, wblk>>>(Wv, wvb, wvs);
    wsplit<<<wgrid, wblk>>>(Wp, wpb, wps);

    // 2. QKV projections (HMMA)
    dim3 ggrid(DOUT / 128, ROWS / 128);   // (8, 32)
    gemm_mma<<<ggrid, 256>>>(xb, xs, wqb, wqs, q);
    gemm_mma<<<ggrid, 256>>>(xb, xs, wkb, wks, k);
    gemm_mma<<<ggrid, 256>>>(xb, xs, wvb, wvs, v);

    // 3. attention
    dim3 attn_grid(SLEN / BR, BATCH * NH);
    attn_kernel<<<attn_grid, 256>>>(q, k, v, ctx);

    // 4. output projection
    fsplit<<<n4 / 256, 256>>>((const float4*)ctx, (uint2*)cb, (uint2*)cs, n4);
    gemm_mma<<<ggrid, 256>>>(cb, cs, wpb, wps, out);
}

// round 8
// speedup vs baseline: 3.7693x; 2.8330x over previous
#include <cuda_runtime.h>
#include <cuda_bf16.h>
#include <cstdint>
#include <math.h>

#define SLEN 2048
#define DIN  1024
#define DOUT 1024
#define NH   16
#define HD   64
#define BATCH 2
#define ROWS (BATCH*SLEN)   // 4096

// ---------------------------------------------------------------------------
// Scratch (allocation-free device globals), all bf16 split pairs
// ---------------------------------------------------------------------------
__device__ __nv_bfloat16 g_xb[(size_t)ROWS*DIN],  g_xs[(size_t)ROWS*DIN];
__device__ __nv_bfloat16 g_qb2[(size_t)ROWS*DOUT], g_qs2[(size_t)ROWS*DOUT];
__device__ __nv_bfloat16 g_kb2[(size_t)ROWS*DOUT], g_ks2[(size_t)ROWS*DOUT];
__device__ __nv_bfloat16 g_vb2[(size_t)ROWS*DOUT], g_vs2[(size_t)ROWS*DOUT];
__device__ __nv_bfloat16 g_cb[(size_t)ROWS*DOUT],  g_cs[(size_t)ROWS*DOUT];
// transposed+split weights [N,K] K-major bf16
__device__ __nv_bfloat16 g_wqb[(size_t)DIN*DOUT], g_wqs[(size_t)DIN*DOUT];
__device__ __nv_bfloat16 g_wkb[(size_t)DIN*DOUT], g_wks[(size_t)DIN*DOUT];
__device__ __nv_bfloat16 g_wvb[(size_t)DIN*DOUT], g_wvs[(size_t)DIN*DOUT];
__device__ __nv_bfloat16 g_wpb[(size_t)DOUT*DOUT], g_wps[(size_t)DOUT*DOUT];

// ---------------------------------------------------------------------------
// mma.sync helpers (sm_80+, plain sm_100-safe)
// ---------------------------------------------------------------------------
__device__ __forceinline__ uint32_t smem_u32(const void* p) {
    uint32_t a;
    asm("{ .reg .u64 t; cvta.to.shared.u64 t, %1; cvt.u32.u64 %0, t; }" : "=r"(a) : "l"(p));
    return a;
}
__device__ __forceinline__ void ldsm4(uint32_t* r, uint32_t addr) {
    asm volatile("ldmatrix.sync.aligned.m8n8.x4.shared.b16 {%0,%1,%2,%3}, [%4];"
                 : "=r"(r[0]), "=r"(r[1]), "=r"(r[2]), "=r"(r[3]) : "r"(addr));
}
__device__ __forceinline__ void ldsm2(uint32_t* r, uint32_t addr) {
    asm volatile("ldmatrix.sync.aligned.m8n8.x2.shared.b16 {%0,%1}, [%2];"
                 : "=r"(r[0]), "=r"(r[1]) : "r"(addr));
}
__device__ __forceinline__ void ldsm2t(uint32_t* r, uint32_t addr) {
    asm volatile("ldmatrix.sync.aligned.m8n8.x2.trans.shared.b16 {%0,%1}, [%2];"
                 : "=r"(r[0]), "=r"(r[1]) : "r"(addr));
}
__device__ __forceinline__ void mma16816(float* d, const uint32_t* a, const uint32_t* b) {
    asm volatile("mma.sync.aligned.m16n8k16.row.col.f32.bf16.bf16.f32 "
                 "{%0,%1,%2,%3}, {%4,%5,%6,%7}, {%8,%9}, {%0,%1,%2,%3};"
                 : "+f"(d[0]), "+f"(d[1]), "+f"(d[2]), "+f"(d[3])
                 : "r"(a[0]), "r"(a[1]), "r"(a[2]), "r"(a[3]), "r"(b[0]), "r"(b[1]));
}
__device__ __forceinline__ uint32_t pack_bf2(float a, float b) {
    __nv_bfloat162 h;
    h.x = __float2bfloat16_rn(a);
    h.y = __float2bfloat16_rn(b);
    return *reinterpret_cast<uint32_t*>(&h);
}
__device__ __forceinline__ void split2(float a, float b, uint32_t& big, uint32_t& sml) {
    __nv_bfloat16 ba = __float2bfloat16_rn(a), bb = __float2bfloat16_rn(b);
    __nv_bfloat162 h; h.x = ba; h.y = bb;
    big = *reinterpret_cast<uint32_t*>(&h);
    sml = pack_bf2(a - __bfloat162float(ba), b - __bfloat162float(bb));
}

// ---------------------------------------------------------------------------
// fsplit: fp32 -> (big, small) bf16 arrays
// ---------------------------------------------------------------------------
__global__ void fsplit(const float4* __restrict__ in, uint2* __restrict__ outb,
                       uint2* __restrict__ outs, int n4) {
    int i = blockIdx.x * blockDim.x + threadIdx.x;
    if (i >= n4) return;
    float4 v = in[i];
    uint2 ob, os;
    split2(v.x, v.y, ob.x, os.x);
    split2(v.z, v.w, ob.y, os.y);
    outb[i] = ob;
    outs[i] = os;
}

// ---------------------------------------------------------------------------
// wsplit: W[K,N] fp32 -> WT big/small [N,K] bf16 (tiled transpose)
// ---------------------------------------------------------------------------
__global__ void wsplit(const float* __restrict__ W, __nv_bfloat16* __restrict__ tb,
                       __nv_bfloat16* __restrict__ ts) {
    __shared__ float t[32][33];
    const int n0 = blockIdx.x * 32, k0 = blockIdx.y * 32;
    const int tx = threadIdx.x, ty = threadIdx.y;   // (32, 8)
#pragma unroll
    for (int i = 0; i < 4; i++)
        t[ty + 8 * i][tx] = W[(size_t)(k0 + ty + 8 * i) * DOUT + n0 + tx];
    __syncthreads();
#pragma unroll
    for (int i = 0; i < 4; i++) {
        const int r = ty + 8 * i;
        float v = t[tx][r];
        __nv_bfloat16 b = __float2bfloat16_rn(v);
        tb[(size_t)(n0 + r) * DIN + k0 + tx] = b;
        ts[(size_t)(n0 + r) * DIN + k0 + tx] =
            __float2bfloat16_rn(v - __bfloat162float(b));
    }
}

// ---------------------------------------------------------------------------
// HMMA split-bf16 GEMM core. Two epilogues: fp32 out, or bf16 big/small out.
// CTA 128x128, BK=32, 8 warps (2m x 4n), warp tile 64x32.
// ---------------------------------------------------------------------------
#define PA 40              // smem pitch in bf16 (80 B); rows are 32 bf16 (64 B)
#define BKC 32

template <bool SPLIT_OUT>
__device__ __forceinline__ void gemm_body(const __nv_bfloat16* __restrict__ Ab,
                                          const __nv_bfloat16* __restrict__ As,
                                          const __nv_bfloat16* __restrict__ Bb,
                                          const __nv_bfloat16* __restrict__ Bs,
                                          float* __restrict__ C,
                                          __nv_bfloat16* __restrict__ Cb,
                                          __nv_bfloat16* __restrict__ Cs) {
    __shared__ __nv_bfloat16 sAb[128 * PA];
    __shared__ __nv_bfloat16 sAs[128 * PA];
    __shared__ __nv_bfloat16 sBb[128 * PA];
    __shared__ __nv_bfloat16 sBs[128 * PA];

    const int tid = threadIdx.x;
    const int wid = tid >> 5, lane = tid & 31;
    const int n0 = blockIdx.x * 128, m0 = blockIdx.y * 128;
    const int warp_m = wid >> 2, warp_n = wid & 3;
    const int m0w = warp_m * 64, n0w = warp_n * 32;

    const uint32_t uAb = smem_u32(sAb), uAs = smem_u32(sAs);
    const uint32_t uBb = smem_u32(sBb), uBs = smem_u32(sBs);

    const int grp = lane >> 3;
    uint32_t aoff[4];
#pragma unroll
    for (int mt = 0; mt < 4; mt++) {
        const int rowA = m0w + mt * 16 + (grp & 1) * 8 + (lane & 7);
        aoff[mt] = (uint32_t)(rowA * (PA * 2) + (grp >> 1) * 16);
    }
    const int grpb = grp & 1;
    uint32_t boff[4];
#pragma unroll
    for (int nt = 0; nt < 4; nt++) {
        const int rowB = n0w + nt * 8 + (lane & 7);
        boff[nt] = (uint32_t)(rowB * (PA * 2) + grpb * 16);
    }

    float acc[16][4];
#pragma unroll
    for (int i = 0; i < 16; i++)
#pragma unroll
        for (int j = 0; j < 4; j++) acc[i][j] = 0.f;

    for (int ch = 0; ch < 1024 / BKC; ch++) {
        const int k0 = ch * BKC;
        __syncthreads();
#pragma unroll
        for (int it = tid; it < 512; it += 256) {
            const int row = it >> 2, u = it & 3;
            const uint32_t so = (uint32_t)(row * PA + u * 8);
            *(uint4*)&sAb[so] = *((const uint4*)(Ab + (size_t)(m0 + row) * 1024 + k0) + u);
            *(uint4*)&sAs[so] = *((const uint4*)(As + (size_t)(m0 + row) * 1024 + k0) + u);
            *(uint4*)&sBb[so] = *((const uint4*)(Bb + (size_t)(n0 + row) * 1024 + k0) + u);
            *(uint4*)&sBs[so] = *((const uint4*)(Bs + (size_t)(n0 + row) * 1024 + k0) + u);
        }
        __syncthreads();

#pragma unroll
        for (int ks = 0; ks < 2; ks++) {
            const uint32_t kb = ks * 32;
            uint32_t fab[4][4], fas[4][4], fbb[4][2], fbs[4][2];
#pragma unroll
            for (int mt = 0; mt < 4; mt++) {
                ldsm4(fab[mt], uAb + aoff[mt] + kb);
                ldsm4(fas[mt], uAs + aoff[mt] + kb);
            }
#pragma unroll
            for (int nt = 0; nt < 4; nt++) {
                ldsm2(fbb[nt], uBb + boff[nt] + kb);
                ldsm2(fbs[nt], uBs + boff[nt] + kb);
            }
#pragma unroll
            for (int mt = 0; mt < 4; mt++)
#pragma unroll
                for (int nt = 0; nt < 4; nt++) {
                    float* d = acc[mt * 4 + nt];
                    mma16816(d, fab[mt], fbb[nt]);
                    mma16816(d, fab[mt], fbs[nt]);
                    mma16816(d, fas[mt], fbb[nt]);
                }
        }
    }

#pragma unroll
    for (int mt = 0; mt < 4; mt++)
#pragma unroll
        for (int nt = 0; nt < 4; nt++) {
            const float* d = acc[mt * 4 + nt];
            const int r0 = m0 + m0w + mt * 16 + (lane >> 2);
            const int c0 = n0 + n0w + nt * 8 + (lane & 3) * 2;
            if (SPLIT_OUT) {
                uint32_t big, sml;
                split2(d[0], d[1], big, sml);
                *(uint32_t*)&Cb[(size_t)r0 * 1024 + c0] = big;
                *(uint32_t*)&Cs[(size_t)r0 * 1024 + c0] = sml;
                split2(d[2], d[3], big, sml);
                *(uint32_t*)&Cb[(size_t)(r0 + 8) * 1024 + c0] = big;
                *(uint32_t*)&Cs[(size_t)(r0 + 8) * 1024 + c0] = sml;
            } else {
                *(float2*)(C + (size_t)r0 * 1024 + c0)       = make_float2(d[0], d[1]);
                *(float2*)(C + (size_t)(r0 + 8) * 1024 + c0) = make_float2(d[2], d[3]);
            }
        }
}

__global__ __launch_bounds__(256) void gemm_mma(const __nv_bfloat16* __restrict__ Ab,
                                                const __nv_bfloat16* __restrict__ As,
                                                const __nv_bfloat16* __restrict__ Bb,
                                                const __nv_bfloat16* __restrict__ Bs,
                                                float* __restrict__ C) {
    gemm_body<false>(Ab, As, Bb, Bs, C, nullptr, nullptr);
}
__global__ __launch_bounds__(256) void gemm_mma_bs(const __nv_bfloat16* __restrict__ Ab,
                                                   const __nv_bfloat16* __restrict__ As,
                                                   const __nv_bfloat16* __restrict__ Bb,
                                                   const __nv_bfloat16* __restrict__ Bs,
                                                   __nv_bfloat16* __restrict__ Cb,
                                                   __nv_bfloat16* __restrict__ Cs) {
    gemm_body<true>(Ab, As, Bb, Bs, nullptr, Cb, Cs);
}

// ---------------------------------------------------------------------------
// HMMA flash attention over contiguous per-(b,h) [SLEN, HD] chunks.
// BR=64 (4 warps x 16 rows), BC=64. 128 threads. All operands bf16 splits.
// Rows are 64 bf16 = 128 B -> pitch PP=72 bf16 (144 B; 16B-aligned,
// 144 mod 128 = 16 keeps ldmatrix 8-row sets conflict-free).
// Q buffers are overlaid with V buffers (Q only needed until frags loaded).
// Static smem = 4 * 9216 = 36.9 KB.
// ---------------------------------------------------------------------------
#define PP 72

__global__ __launch_bounds__(128) void attn_mma(const __nv_bfloat16* __restrict__ qb,
                                                const __nv_bfloat16* __restrict__ qs,
                                                const __nv_bfloat16* __restrict__ kb,
                                                const __nv_bfloat16* __restrict__ ks,
                                                const __nv_bfloat16* __restrict__ vb,
                                                const __nv_bfloat16* __restrict__ vs,
                                                __nv_bfloat16* __restrict__ cb,
                                                __nv_bfloat16* __restrict__ cs) {
    __shared__ __nv_bfloat16 sBuf0[64 * PP];   // Qb, then Vb
    __shared__ __nv_bfloat16 sBuf1[64 * PP];   // Qs, then Vs
    __shared__ __nv_bfloat16 sKb[64 * PP];
    __shared__ __nv_bfloat16 sKs[64 * PP];

    const int tid = threadIdx.x;
    const int wid = tid >> 5, lane = tid & 31;
    const int qx = blockIdx.x;
    const size_t chunk = (size_t)blockIdx.y * (SLEN * HD);
    const int qi0 = qx * 64;
    const int m0w = wid * 16;

    // load Q tile (64 rows x 64 bf16 = 8 uint4 per row) into sBuf0/sBuf1
    for (int it = tid; it < 512; it += 128) {
        const int row = it >> 3, u = it & 7;
        const uint32_t so = (uint32_t)(row * PP + u * 8);
        *(uint4*)&sBuf0[so] = *((const uint4*)(qb + chunk + (size_t)(qi0 + row) * HD) + u);
        *(uint4*)&sBuf1[so] = *((const uint4*)(qs + chunk + (size_t)(qi0 + row) * HD) + u);
    }
    __syncthreads();

    const int grp = lane >> 3;
    const uint32_t qoff =
        (uint32_t)((m0w + (grp & 1) * 8 + (lane & 7)) * (PP * 2) + (grp >> 1) * 16);
    uint32_t fqb[4][4], fqs[4][4];
    {
        const uint32_t uQb = smem_u32(sBuf0), uQs = smem_u32(sBuf1);
#pragma unroll
        for (int k4 = 0; k4 < 4; k4++) {
            ldsm4(fqb[k4], uQb + qoff + k4 * 32);
            ldsm4(fqs[k4], uQs + qoff + k4 * 32);
        }
    }

    const uint32_t uKb = smem_u32(sKb), uKs = smem_u32(sKs);
    const uint32_t uVb = smem_u32(sBuf0), uVs = smem_u32(sBuf1);

    // per-thread rows r0 = m0w + lane>>2, r1 = r0+8
    float m0v = -1e30f, m1v = -1e30f, l0 = 0.f, l1 = 0.f;
    float o[8][4];
#pragma unroll
    for (int i = 0; i < 8; i++)
#pragma unroll
        for (int j = 0; j < 4; j++) o[i][j] = 0.f;

    const uint32_t koffb =
        (uint32_t)((lane & 7) * (PP * 2) + ((lane >> 3) & 1) * 16);
    const uint32_t voffb =
        (uint32_t)(((lane & 7) + ((lane >> 3) & 1) * 8) * (PP * 2));

    const int ntiles = qx + 1;
    for (int kt = 0; kt < ntiles; kt++) {
        const int kj0 = kt * 64;
        __syncthreads();   // Q frags done (first iter) / prev-tile readers done
        for (int it = tid; it < 512; it += 128) {
            const int row = it >> 3, u = it & 7;
            const uint32_t so = (uint32_t)(row * PP + u * 8);
            *(uint4*)&sKb[so]   = *((const uint4*)(kb + chunk + (size_t)(kj0 + row) * HD) + u);
            *(uint4*)&sKs[so]   = *((const uint4*)(ks + chunk + (size_t)(kj0 + row) * HD) + u);
            *(uint4*)&sBuf0[so] = *((const uint4*)(vb + chunk + (size_t)(kj0 + row) * HD) + u);
            *(uint4*)&sBuf1[so] = *((const uint4*)(vs + chunk + (size_t)(kj0 + row) * HD) + u);
        }
        __syncthreads();

        // ---- S = Q K^T (f32 frags) ----
        float s[8][4];
#pragma unroll
        for (int i = 0; i < 8; i++)
#pragma unroll
            for (int j = 0; j < 4; j++) s[i][j] = 0.f;
#pragma unroll
        for (int k4 = 0; k4 < 4; k4++) {
#pragma unroll
            for (int nt = 0; nt < 8; nt++) {
                const uint32_t off = koffb + (uint32_t)(nt * 8 * (PP * 2)) + k4 * 32;
                uint32_t b0[2], b1[2];
                ldsm2(b0, uKb + off);
                ldsm2(b1, uKs + off);
                mma16816(s[nt], fqb[k4], b0);
                mma16816(s[nt], fqb[k4], b1);
                mma16816(s[nt], fqs[k4], b0);
            }
        }

        // ---- scale + causal mask (diag tile only) + online softmax ----
#pragma unroll
        for (int nt = 0; nt < 8; nt++)
#pragma unroll
            for (int j = 0; j < 4; j++) s[nt][j] *= 0.125f;

        if (kt == qx) {
            const int row0 = qi0 + m0w + (lane >> 2);
            const int row1 = row0 + 8;
#pragma unroll
            for (int nt = 0; nt < 8; nt++) {
                const int c = kj0 + nt * 8 + (lane & 3) * 2;
                if (c > row0)     s[nt][0] = -1e30f;
                if (c + 1 > row0) s[nt][1] = -1e30f;
                if (c > row1)     s[nt][2] = -1e30f;
                if (c + 1 > row1) s[nt][3] = -1e30f;
            }
        }

        float tmax0 = -1e30f, tmax1 = -1e30f;
#pragma unroll
        for (int nt = 0; nt < 8; nt++) {
            tmax0 = fmaxf(tmax0, fmaxf(s[nt][0], s[nt][1]));
            tmax1 = fmaxf(tmax1, fmaxf(s[nt][2], s[nt][3]));
        }
        tmax0 = fmaxf(tmax0, __shfl_xor_sync(0xffffffffu, tmax0, 1));
        tmax0 = fmaxf(tmax0, __shfl_xor_sync(0xffffffffu, tmax0, 2));
        tmax1 = fmaxf(tmax1, __shfl_xor_sync(0xffffffffu, tmax1, 1));
        tmax1 = fmaxf(tmax1, __shfl_xor_sync(0xffffffffu, tmax1, 2));

        const float mnew0 = fmaxf(m0v, tmax0), mnew1 = fmaxf(m1v, tmax1);
        const float corr0 = __expf(m0v - mnew0), corr1 = __expf(m1v - mnew1);

        float ts0 = 0.f, ts1 = 0.f;
#pragma unroll
        for (int nt = 0; nt < 8; nt++) {
            s[nt][0] = __expf(s[nt][0] - mnew0);
            s[nt][1] = __expf(s[nt][1] - mnew0);
            s[nt][2] = __expf(s[nt][2] - mnew1);
            s[nt][3] = __expf(s[nt][3] - mnew1);
            ts0 += s[nt][0] + s[nt][1];
            ts1 += s[nt][2] + s[nt][3];
        }
        ts0 += __shfl_xor_sync(0xffffffffu, ts0, 1);
        ts0 += __shfl_xor_sync(0xffffffffu, ts0, 2);
        ts1 += __shfl_xor_sync(0xffffffffu, ts1, 1);
        ts1 += __shfl_xor_sync(0xffffffffu, ts1, 2);
        l0 = l0 * corr0 + ts0;
        l1 = l1 * corr1 + ts1;
        m0v = mnew0;
        m1v = mnew1;
#pragma unroll
        for (int nt = 0; nt < 8; nt++) {
            o[nt][0] *= corr0;
            o[nt][1] *= corr0;
            o[nt][2] *= corr1;
            o[nt][3] *= corr1;
        }

        // ---- ctx += P V (P split in registers, V via ldmatrix.trans) ----
#pragma unroll
        for (int kj = 0; kj < 4; kj++) {
            const float* t0 = s[2 * kj];
            const float* t1 = s[2 * kj + 1];
            uint32_t pb[4], ps[4];
            split2(t0[0], t0[1], pb[0], ps[0]);
            split2(t0[2], t0[3], pb[1], ps[1]);
            split2(t1[0], t1[1], pb[2], ps[2]);
            split2(t1[2], t1[3], pb[3], ps[3]);
#pragma unroll
            for (int nt = 0; nt < 8; nt++) {
                const uint32_t voff =
                    voffb + (uint32_t)(kj * 16 * (PP * 2)) + (uint32_t)(nt * 16);
                uint32_t b0[2], b1[2];
                ldsm2t(b0, uVb + voff);
                ldsm2t(b1, uVs + voff);
                mma16816(o[nt], pb, b0);
                mma16816(o[nt], pb, b1);
                mma16816(o[nt], ps, b0);
            }
        }
    }

    // ---- epilogue: normalize, split to bf16 big/small ----
    const float inv0 = 1.f / l0, inv1 = 1.f / l1;
    const int r0g = qi0 + m0w + (lane >> 2);
#pragma unroll
    for (int nt = 0; nt < 8; nt++) {
        const int c0 = nt * 8 + (lane & 3) * 2;
        uint32_t big, sml;
        split2(o[nt][0] * inv0, o[nt][1] * inv0, big, sml);
        *(uint32_t*)&cb[chunk + (size_t)r0g * HD + c0] = big;
        *(uint32_t*)&cs[chunk + (size_t)r0g * HD + c0] = sml;
        split2(o[nt][2] * inv1, o[nt][3] * inv1, big, sml);
        *(uint32_t*)&cb[chunk + (size_t)(r0g + 8) * HD + c0] = big;
        *(uint32_t*)&cs[chunk + (size_t)(r0g + 8) * HD + c0] = sml;
    }
}

// ---------------------------------------------------------------------------
extern "C" void kernel_launch(void* const* d_in, const int* in_sizes, int n_in,
                              void* d_out, int out_size) {
    const float* x  = (const float*)d_in[0];
    const float* Wq = (const float*)d_in[1];
    const float* Wk = (const float*)d_in[2];
    const float* Wv = (const float*)d_in[3];
    const float* Wp = (const float*)d_in[4];
    float* out = (float*)d_out;

    __nv_bfloat16 *xb, *xs, *qb, *qs, *kb, *ks, *vb, *vs, *cb, *cs;
    cudaGetSymbolAddress((void**)&xb, g_xb);
    cudaGetSymbolAddress((void**)&xs, g_xs);
    cudaGetSymbolAddress((void**)&qb, g_qb2);
    cudaGetSymbolAddress((void**)&qs, g_qs2);
    cudaGetSymbolAddress((void**)&kb, g_kb2);
    cudaGetSymbolAddress((void**)&ks, g_ks2);
    cudaGetSymbolAddress((void**)&vb, g_vb2);
    cudaGetSymbolAddress((void**)&vs, g_vs2);
    cudaGetSymbolAddress((void**)&cb, g_cb);
    cudaGetSymbolAddress((void**)&cs, g_cs);
    __nv_bfloat16 *wqb, *wqs, *wkb, *wks, *wvb, *wvs, *wpb, *wps;
    cudaGetSymbolAddress((void**)&wqb, g_wqb);
    cudaGetSymbolAddress((void**)&wqs, g_wqs);
    cudaGetSymbolAddress((void**)&wkb, g_wkb);
    cudaGetSymbolAddress((void**)&wks, g_wks);
    cudaGetSymbolAddress((void**)&wvb, g_wvb);
    cudaGetSymbolAddress((void**)&wvs, g_wvs);
    cudaGetSymbolAddress((void**)&wpb, g_wpb);
    cudaGetSymbolAddress((void**)&wps, g_wps);

    // 1. split x, transpose+split weights
    const int n4 = ROWS * DIN / 4;
    fsplit<<<n4 / 256, 256>>>((const float4*)x, (uint2*)xb, (uint2*)xs, n4);
    dim3 wgrid(32, 32), wblk(32, 8);
    wsplit<<<wgrid, wblk>>>(Wq, wqb, wqs);
    wsplit<<<wgrid, wblk>>>(Wk, wkb, wks);
    wsplit<<<wgrid, wblk>>>(Wv, wvb, wvs);
    wsplit<<<wgrid, wblk>>>(Wp, wpb, wps);

    // 2. QKV projections -> bf16 splits directly
    dim3 ggrid(DOUT / 128, ROWS / 128);   // (8, 32)
    gemm_mma_bs<<<ggrid, 256>>>(xb, xs, wqb, wqs, qb, qs);
    gemm_mma_bs<<<ggrid, 256>>>(xb, xs, wkb, wks, kb, ks);
    gemm_mma_bs<<<ggrid, 256>>>(xb, xs, wvb, wvs, vb, vs);

    // 3. HMMA flash attention -> cb/cs bf16 splits
    dim3 agrid(SLEN / 64, BATCH * NH);    // (32, 32)
    attn_mma<<<agrid, 128>>>(qb, qs, kb, ks, vb, vs, cb, cs);

    // 4. output projection (fp32 out)
    gemm_mma<<<ggrid, 256>>>(cb, cs, wpb, wps, out);
}